// round 11
// baseline (speedup 1.0000x reference)
#include <cuda_runtime.h>
#include <cstdint>

#define N_NODES 100000
#define E_EDGES 1600000
#define F       128
#define C_OUT   64

// ---- device scratch ----
__device__ int   g_cnt[N_NODES];                 // in-degree histogram (excl. self)
__device__ int   g_ptr[N_NODES + 1];             // CSR row pointers (by target)
__device__ int   g_pos[N_NODES];                 // fill cursors
__device__ int   g_bsum[128];                    // per-block sums from scan1 (nbs<=128)
__device__ int   g_csr[E_EDGES];                 // source node per CSR slot
__device__ float g_dinv[N_NODES];
__device__ float g_wcomb[F * C_OUT];             // W_gcn @ W_fc^T
__device__ float g_xws[(size_t)N_NODES * C_OUT]; // dinv * (x @ Wcomb)
__device__ float g_bfc2[C_OUT];                  // b_fc + W_fc @ b_gcn

// ==================== fused setup: wcomb + bfc2 + zero cnt ====================
__global__ void k_setup(const float* __restrict__ Wg, const float* __restrict__ Wfc,
                        const float* __restrict__ bgcn, const float* __restrict__ bfc,
                        int n) {
    int b = blockIdx.x;
    int t = threadIdx.x;
    int lane = t & 31;
    int w = t >> 5;
    if (b < 1024) {
        int idx = b * 8 + w;                  // 0..8191
        int k = idx >> 6, c = idx & 63;
        const float* wg = Wg + k * F;
        const float* wf = Wfc + c * F;
        float s = wg[lane] * wf[lane];
        s = fmaf(wg[lane + 32], wf[lane + 32], s);
        s = fmaf(wg[lane + 64], wf[lane + 64], s);
        s = fmaf(wg[lane + 96], wf[lane + 96], s);
#pragma unroll
        for (int o = 16; o > 0; o >>= 1) s += __shfl_xor_sync(0xffffffffu, s, o);
        if (lane == 0) g_wcomb[idx] = s;
        return;
    }
    if (b == 1024) {
#pragma unroll
        for (int cc = 0; cc < 8; ++cc) {
            int c = w * 8 + cc;
            const float* wf = Wfc + c * F;
            float s = bgcn[lane] * wf[lane];
            s = fmaf(bgcn[lane + 32], wf[lane + 32], s);
            s = fmaf(bgcn[lane + 64], wf[lane + 64], s);
            s = fmaf(bgcn[lane + 96], wf[lane + 96], s);
#pragma unroll
            for (int o = 16; o > 0; o >>= 1) s += __shfl_xor_sync(0xffffffffu, s, o);
            if (lane == 0) g_bfc2[c] = s + bfc[c];
        }
        return;
    }
    // zero g_cnt: 1024 ints per block
    int base = (b - 1025) * 1024 + t * 4;
    if (base + 3 < n) *(int4*)&g_cnt[base] = make_int4(0, 0, 0, 0);
    else for (int j = base; j < n; ++j) g_cnt[j] = 0;
}

// ==================== histogram over targets ====================
__global__ void k_hist(const int* __restrict__ col, int e) {
    int base = (blockIdx.x * blockDim.x + threadIdx.x) * 4;
    if (base >= e) return;
    if (base + 3 < e) {
        int4 c = *(const int4*)&col[base];
        atomicAdd(&g_cnt[c.x], 1);
        atomicAdd(&g_cnt[c.y], 1);
        atomicAdd(&g_cnt[c.z], 1);
        atomicAdd(&g_cnt[c.w], 1);
    } else {
        for (int j = base; j < e; ++j) atomicAdd(&g_cnt[col[j]], 1);
    }
}

// ==================== scan pass 1: per-block local scan + block sums ====================
__global__ void k_scan1(int n) {
    __shared__ int wsh[8];
    __shared__ int woff[8];
    int t = threadIdx.x, b = blockIdx.x;
    int base = b * 1024 + t * 4;
    int x0 = 0, x1 = 0, x2 = 0, x3 = 0;
    if (base + 3 < n) {
        int4 v = *(const int4*)&g_cnt[base];
        x0 = v.x; x1 = v.y; x2 = v.z; x3 = v.w;
    } else if (base < n) {
        x0 = g_cnt[base];
        if (base + 1 < n) x1 = g_cnt[base + 1];
        if (base + 2 < n) x2 = g_cnt[base + 2];
    }
    int s0 = x0, s1 = s0 + x1, s2 = s1 + x2, s3 = s2 + x3;
    int lane = t & 31, w = t >> 5;
    int ws = s3;
#pragma unroll
    for (int o = 1; o < 32; o <<= 1) {
        int u = __shfl_up_sync(0xffffffffu, ws, o);
        if (lane >= o) ws += u;
    }
    if (lane == 31) wsh[w] = ws;
    __syncthreads();
    if (t == 0) {
        int acc = 0;
#pragma unroll
        for (int i = 0; i < 8; ++i) { woff[i] = acc; acc += wsh[i]; }
        g_bsum[b] = acc;
    }
    __syncthreads();
    int excl = woff[w] + ws - s3;
    if (base < n)     g_ptr[base]     = excl;
    if (base + 1 < n) g_ptr[base + 1] = excl + s0;
    if (base + 2 < n) g_ptr[base + 2] = excl + s1;
    if (base + 3 < n) g_ptr[base + 3] = excl + s2;
}

// ==================== scan pass 2 (fused): add block offset; pos/dinv ====================
__global__ void k_scan3(int n, int e, int nbs) {
    __shared__ int s_off;
    __shared__ int psum[4];
    int t = threadIdx.x, b = blockIdx.x;
    int lane = t & 31;
    if (t < 128) {
        int v = (t < b && t < nbs) ? g_bsum[t] : 0;
#pragma unroll
        for (int o = 16; o > 0; o >>= 1) v += __shfl_xor_sync(0xffffffffu, v, o);
        if (lane == 0) psum[t >> 5] = v;
    }
    __syncthreads();
    if (t == 0) s_off = psum[0] + psum[1] + psum[2] + psum[3];
    __syncthreads();
    int off = s_off;
    int base = b * 1024 + t * 4;
#pragma unroll
    for (int j = 0; j < 4; ++j) {
        int i = base + j;
        if (i < n) {
            int p = g_ptr[i] + off;
            g_ptr[i] = p;
            g_pos[i] = p;
            g_dinv[i] = rsqrtf((float)(g_cnt[i] + 1));
        }
    }
    if (b == 0 && t == 0) g_ptr[n] = e;
}

// ==================== CSR fill (4 edges/thread) ====================
__global__ void k_fill(const int* __restrict__ ei, int e) {
    int i = (blockIdx.x * blockDim.x + threadIdx.x) * 4;
    if (i >= e) return;
    if (i + 3 < e) {
        int4 rows = *(const int4*)&ei[i];
        int4 cols = *(const int4*)&ei[e + i];
        int p0 = atomicAdd(&g_pos[cols.x], 1); g_csr[p0] = rows.x;
        int p1 = atomicAdd(&g_pos[cols.y], 1); g_csr[p1] = rows.y;
        int p2 = atomicAdd(&g_pos[cols.z], 1); g_csr[p2] = rows.z;
        int p3 = atomicAdd(&g_pos[cols.w], 1); g_csr[p3] = rows.w;
    } else {
        for (int j = i; j < e; ++j) {
            int p = atomicAdd(&g_pos[ei[e + j]], 1);
            g_csr[p] = ei[j];
        }
    }
}

// ==================== GEMM: xws = dinv * (x @ Wcomb) ====================
__global__ void k_xw(const float* __restrict__ x, int n) {
    extern __shared__ float sh[];
    float* Wsm = sh;               // 128*64 = 32 KB  [k][c]
    float* Xsm = sh + F * C_OUT;   // 128*128 = 64 KB [r][k]

    int t = threadIdx.x;
    for (int i = t; i < (F * C_OUT) / 4; i += 256)
        ((float4*)Wsm)[i] = ((const float4*)g_wcomb)[i];

    int base = blockIdx.x * 128;
    for (int i = t; i < 128 * 32; i += 256) {
        int rr = i >> 5, cc = i & 31;
        int r = base + rr;
        float4 v = make_float4(0.f, 0.f, 0.f, 0.f);
        if (r < n) v = ((const float4*)x)[(size_t)r * 32 + cc];
        ((float4*)Xsm)[i] = v;
    }
    __syncthreads();

    int tx = t & 15;
    int ty = t >> 4;
    int c0 = tx * 4, r0 = ty * 8;

    float acc[8][4];
#pragma unroll
    for (int i = 0; i < 8; ++i)
#pragma unroll
        for (int j = 0; j < 4; ++j) acc[i][j] = 0.f;

#pragma unroll 4
    for (int k = 0; k < F; ++k) {
        float4 w = *(const float4*)&Wsm[k * C_OUT + c0];
#pragma unroll
        for (int i = 0; i < 8; ++i) {
            float xv = Xsm[(r0 + i) * F + k];
            acc[i][0] = fmaf(xv, w.x, acc[i][0]);
            acc[i][1] = fmaf(xv, w.y, acc[i][1]);
            acc[i][2] = fmaf(xv, w.z, acc[i][2]);
            acc[i][3] = fmaf(xv, w.w, acc[i][3]);
        }
    }

#pragma unroll
    for (int i = 0; i < 8; ++i) {
        int r = base + r0 + i;
        if (r < n) {
            float dv = g_dinv[r];
            float4 v;
            v.x = dv * acc[i][0];
            v.y = dv * acc[i][1];
            v.z = dv * acc[i][2];
            v.w = dv * acc[i][3];
            *(float4*)&g_xws[(size_t)r * C_OUT + c0] = v;
        }
    }
}

// ==================== gather: out = dinv_r*(xws[r] + sum xws[nbr]) + bfc2 ====================
// 16 threads per node; broadcast index loads (L1 broadcast = free) with 2-deep prefetch
__global__ void k_gather(float* __restrict__ out, int n) {
    int gt = blockIdx.x * blockDim.x + threadIdx.x;
    int r = gt >> 4;
    if (r >= n) return;
    int l4 = (gt & 15) * 4;

    int p0 = __ldg(&g_ptr[r]);
    int p1 = __ldg(&g_ptr[r + 1]);

    float4 acc = *(const float4*)&g_xws[(size_t)r * C_OUT + l4];  // self-loop

    int j = p0;
    int i0 = (j     < p1) ? __ldg(&g_csr[j])     : 0;
    int i1 = (j + 1 < p1) ? __ldg(&g_csr[j + 1]) : 0;
    while (j < p1) {
        int idx = i0;
        i0 = i1;
        i1 = (j + 2 < p1) ? __ldg(&g_csr[j + 2]) : 0;
        ++j;
        float4 v = *(const float4*)&g_xws[(size_t)idx * C_OUT + l4];
        acc.x += v.x; acc.y += v.y; acc.z += v.z; acc.w += v.w;
    }

    float dvr = __ldg(&g_dinv[r]);
    float4 b = *(const float4*)&g_bfc2[l4];
    float4 o;
    o.x = fmaf(dvr, acc.x, b.x);
    o.y = fmaf(dvr, acc.y, b.y);
    o.z = fmaf(dvr, acc.z, b.z);
    o.w = fmaf(dvr, acc.w, b.w);
    *(float4*)&out[(size_t)r * C_OUT + l4] = o;
}

// ==================== launch (single stream — harness-safe) ====================
extern "C" void kernel_launch(void* const* d_in, const int* in_sizes, int n_in,
                              void* d_out, int out_size) {
    const float* x    = (const float*)d_in[0];
    const int*   ei   = (const int*)d_in[1];
    const float* Wgcn = (const float*)d_in[2];
    const float* bgcn = (const float*)d_in[3];
    const float* Wfc  = (const float*)d_in[4];
    const float* bfc  = (const float*)d_in[5];
    float* out = (float*)d_out;

    int n = in_sizes[0] / F;       // 100000
    int e = in_sizes[1] / 2;       // 1600000

    static bool attr_set = false;
    if (!attr_set) {
        cudaFuncSetAttribute(k_xw, cudaFuncAttributeMaxDynamicSharedMemorySize,
                             (F * C_OUT + 128 * F) * 4);
        attr_set = true;
    }

    int nbs = (n + 1023) / 1024;   // 98 (<=128)

    k_setup<<<1024 + 1 + nbs, 256>>>(Wgcn, Wfc, bgcn, bfc, n);

    int hthreads = (e + 3) / 4;
    k_hist<<<(hthreads + 255) / 256, 256>>>(ei + e, e);

    k_scan1<<<nbs, 256>>>(n);
    k_scan3<<<nbs, 256>>>(n, e, nbs);

    int fthreads = (e + 3) / 4;
    k_fill<<<(fthreads + 255) / 256, 256>>>(ei, e);

    int gemm_blocks = (n + 127) / 128;
    k_xw<<<gemm_blocks, 256, (F * C_OUT + 128 * F) * 4>>>(x, n);

    k_gather<<<(n * 16 + 255) / 256, 256>>>(out, n);
}

// round 12
// speedup vs baseline: 1.3737x; 1.3737x over previous
#include <cuda_runtime.h>
#include <cstdint>

#define N_NODES 100000
#define E_EDGES 1600000
#define F       128
#define C_OUT   64

// ---- device scratch ----
__device__ int   g_cnt[N_NODES];                 // in-degree histogram (excl. self)
__device__ int   g_ptr[N_NODES + 1];             // CSR row pointers (by target)
__device__ int   g_pos[N_NODES];                 // fill cursors
__device__ int   g_bsum[256];
__device__ int   g_boff[256];
__device__ int   g_csr[E_EDGES];                 // source node per CSR slot (6.4 MB)
__device__ float g_dinv[N_NODES];
__device__ float g_wcomb[F * C_OUT];             // W_gcn @ W_fc^T
__device__ float g_xws[(size_t)N_NODES * C_OUT]; // dinv * (x @ Wcomb)  (25.6 MB)
__device__ float g_bfc2[C_OUT];                  // b_fc + W_fc @ b_gcn

// ==================== fused setup: wcomb + bfc2 + zero cnt ====================
// blocks [0,1024): wcomb (1 warp/output).  block 1024: bfc2.  blocks >1024: zero g_cnt.
__global__ void k_setup(const float* __restrict__ Wg, const float* __restrict__ Wfc,
                        const float* __restrict__ bgcn, const float* __restrict__ bfc,
                        int n) {
    int b = blockIdx.x;
    int t = threadIdx.x;
    int lane = t & 31;
    int w = t >> 5;
    if (b < 1024) {
        int idx = b * 8 + w;                  // 0..8191
        int k = idx >> 6, c = idx & 63;
        const float* wg = Wg + k * F;
        const float* wf = Wfc + c * F;
        float s = wg[lane] * wf[lane];
        s = fmaf(wg[lane + 32], wf[lane + 32], s);
        s = fmaf(wg[lane + 64], wf[lane + 64], s);
        s = fmaf(wg[lane + 96], wf[lane + 96], s);
#pragma unroll
        for (int o = 16; o > 0; o >>= 1) s += __shfl_xor_sync(0xffffffffu, s, o);
        if (lane == 0) g_wcomb[idx] = s;
        return;
    }
    if (b == 1024) {
#pragma unroll
        for (int cc = 0; cc < 8; ++cc) {
            int c = w * 8 + cc;
            const float* wf = Wfc + c * F;
            float s = bgcn[lane] * wf[lane];
            s = fmaf(bgcn[lane + 32], wf[lane + 32], s);
            s = fmaf(bgcn[lane + 64], wf[lane + 64], s);
            s = fmaf(bgcn[lane + 96], wf[lane + 96], s);
#pragma unroll
            for (int o = 16; o > 0; o >>= 1) s += __shfl_xor_sync(0xffffffffu, s, o);
            if (lane == 0) g_bfc2[c] = s + bfc[c];
        }
        return;
    }
    // zero g_cnt: 1024 ints per block
    int base = (b - 1025) * 1024 + t * 4;
    if (base + 3 < n) *(int4*)&g_cnt[base] = make_int4(0, 0, 0, 0);
    else for (int j = base; j < n; ++j) g_cnt[j] = 0;
}

// ==================== histogram over targets ====================
__global__ void k_hist(const int* __restrict__ col, int e) {
    int base = (blockIdx.x * blockDim.x + threadIdx.x) * 4;
    if (base >= e) return;
    if (base + 3 < e) {
        int4 c = *(const int4*)&col[base];
        atomicAdd(&g_cnt[c.x], 1);
        atomicAdd(&g_cnt[c.y], 1);
        atomicAdd(&g_cnt[c.z], 1);
        atomicAdd(&g_cnt[c.w], 1);
    } else {
        for (int j = base; j < e; ++j) atomicAdd(&g_cnt[col[j]], 1);
    }
}

// ==================== exclusive scan (3 kernels) ====================
__global__ void k_scan1(int n) {
    __shared__ int wsh[8];
    __shared__ int woff[8];
    int t = threadIdx.x, b = blockIdx.x;
    int base = b * 1024 + t * 4;
    int x0 = 0, x1 = 0, x2 = 0, x3 = 0;
    if (base + 3 < n) {
        int4 v = *(const int4*)&g_cnt[base];
        x0 = v.x; x1 = v.y; x2 = v.z; x3 = v.w;
    } else if (base < n) {
        x0 = g_cnt[base];
        if (base + 1 < n) x1 = g_cnt[base + 1];
        if (base + 2 < n) x2 = g_cnt[base + 2];
    }
    int s0 = x0, s1 = s0 + x1, s2 = s1 + x2, s3 = s2 + x3;
    int lane = t & 31, w = t >> 5;
    int ws = s3;
#pragma unroll
    for (int o = 1; o < 32; o <<= 1) {
        int u = __shfl_up_sync(0xffffffffu, ws, o);
        if (lane >= o) ws += u;
    }
    if (lane == 31) wsh[w] = ws;
    __syncthreads();
    if (t == 0) {
        int acc = 0;
#pragma unroll
        for (int i = 0; i < 8; ++i) { woff[i] = acc; acc += wsh[i]; }
        g_bsum[b] = acc;
    }
    __syncthreads();
    int excl = woff[w] + ws - s3;
    if (base < n)     g_ptr[base]     = excl;
    if (base + 1 < n) g_ptr[base + 1] = excl + s0;
    if (base + 2 < n) g_ptr[base + 2] = excl + s1;
    if (base + 3 < n) g_ptr[base + 3] = excl + s2;
}

__global__ void k_scan2(int nb) {
    __shared__ int wsh[8];
    __shared__ int woff[8];
    int t = threadIdx.x;
    int v = (t < nb) ? g_bsum[t] : 0;
    int lane = t & 31, w = t >> 5;
    int ws = v;
#pragma unroll
    for (int o = 1; o < 32; o <<= 1) {
        int u = __shfl_up_sync(0xffffffffu, ws, o);
        if (lane >= o) ws += u;
    }
    if (lane == 31) wsh[w] = ws;
    __syncthreads();
    if (t == 0) {
        int acc = 0;
#pragma unroll
        for (int i = 0; i < 8; ++i) { woff[i] = acc; acc += wsh[i]; }
    }
    __syncthreads();
    if (t < nb) g_boff[t] = woff[w] + ws - v;
}

__global__ void k_scan3(int n, int e) {
    int t = threadIdx.x, b = blockIdx.x;
    int off = g_boff[b];
    int base = b * 1024 + t * 4;
#pragma unroll
    for (int j = 0; j < 4; ++j) {
        int i = base + j;
        if (i < n) {
            int p = g_ptr[i] + off;
            g_ptr[i] = p;
            g_pos[i] = p;
            g_dinv[i] = rsqrtf((float)(g_cnt[i] + 1));
        }
    }
    if (b == 0 && t == 0) g_ptr[n] = e;
}

// ==================== CSR fill: bucket source rows by target ====================
__global__ void k_fill(const int* __restrict__ ei, int e) {
    int i = (blockIdx.x * blockDim.x + threadIdx.x) * 2;
    if (i >= e) return;
    int2 rows = *(const int2*)&ei[i];       // i even -> 8B aligned
    int2 cols = *(const int2*)&ei[e + i];   // e even -> 8B aligned
    int p0 = atomicAdd(&g_pos[cols.x], 1);
    g_csr[p0] = rows.x;
    if (i + 1 < e) {
        int p1 = atomicAdd(&g_pos[cols.y], 1);
        g_csr[p1] = rows.y;
    }
}

// ==================== GEMM: xws = dinv * (x @ Wcomb) ====================
// tile: 128 rows x 64 cols, 256 threads, each thread 8 rows x 4 cols
__global__ void k_xw(const float* __restrict__ x, int n) {
    extern __shared__ float sh[];
    float* Wsm = sh;               // 128*64 = 32 KB  [k][c]
    float* Xsm = sh + F * C_OUT;   // 128*128 = 64 KB [r][k]

    int t = threadIdx.x;
    for (int i = t; i < (F * C_OUT) / 4; i += 256)
        ((float4*)Wsm)[i] = ((const float4*)g_wcomb)[i];

    int base = blockIdx.x * 128;
    for (int i = t; i < 128 * 32; i += 256) {
        int rr = i >> 5, cc = i & 31;
        int r = base + rr;
        float4 v = make_float4(0.f, 0.f, 0.f, 0.f);
        if (r < n) v = ((const float4*)x)[(size_t)r * 32 + cc];
        ((float4*)Xsm)[i] = v;
    }
    __syncthreads();

    int tx = t & 15;
    int ty = t >> 4;
    int c0 = tx * 4, r0 = ty * 8;

    float acc[8][4];
#pragma unroll
    for (int i = 0; i < 8; ++i)
#pragma unroll
        for (int j = 0; j < 4; ++j) acc[i][j] = 0.f;

#pragma unroll 4
    for (int k = 0; k < F; ++k) {
        float4 w = *(const float4*)&Wsm[k * C_OUT + c0];
#pragma unroll
        for (int i = 0; i < 8; ++i) {
            float xv = Xsm[(r0 + i) * F + k];
            acc[i][0] = fmaf(xv, w.x, acc[i][0]);
            acc[i][1] = fmaf(xv, w.y, acc[i][1]);
            acc[i][2] = fmaf(xv, w.z, acc[i][2]);
            acc[i][3] = fmaf(xv, w.w, acc[i][3]);
        }
    }

#pragma unroll
    for (int i = 0; i < 8; ++i) {
        int r = base + r0 + i;
        if (r < n) {
            float dv = g_dinv[r];
            float4 v;
            v.x = dv * acc[i][0];
            v.y = dv * acc[i][1];
            v.z = dv * acc[i][2];
            v.w = dv * acc[i][3];
            *(float4*)&g_xws[(size_t)r * C_OUT + c0] = v;
        }
    }
}

// ==================== gather + epilogue: out = dinv*(self + sum nbrs) + bfc2 ====================
// 16 threads per node, each owns one float4 column slot
__global__ void k_gather(float* __restrict__ out, int n) {
    int gt = blockIdx.x * blockDim.x + threadIdx.x;
    int r = gt >> 4;
    if (r >= n) return;
    int l4 = (gt & 15) * 4;

    int p0 = __ldg(&g_ptr[r]);
    int p1 = __ldg(&g_ptr[r + 1]);

    float4 acc = *(const float4*)&g_xws[(size_t)r * C_OUT + l4];  // self-loop

    int j = p0;
    int nxt = (j < p1) ? __ldg(&g_csr[j]) : 0;
    while (j < p1) {
        int idx = nxt;
        ++j;
        nxt = (j < p1) ? __ldg(&g_csr[j]) : 0;
        float4 v = *(const float4*)&g_xws[(size_t)idx * C_OUT + l4];
        acc.x += v.x; acc.y += v.y; acc.z += v.z; acc.w += v.w;
    }

    float dv = __ldg(&g_dinv[r]);
    float4 b = *(const float4*)&g_bfc2[l4];
    float4 o;
    o.x = fmaf(dv, acc.x, b.x);
    o.y = fmaf(dv, acc.y, b.y);
    o.z = fmaf(dv, acc.z, b.z);
    o.w = fmaf(dv, acc.w, b.w);
    *(float4*)&out[(size_t)r * C_OUT + l4] = o;
}

// ==================== launch ====================
extern "C" void kernel_launch(void* const* d_in, const int* in_sizes, int n_in,
                              void* d_out, int out_size) {
    const float* x    = (const float*)d_in[0];
    const int*   ei   = (const int*)d_in[1];
    const float* Wgcn = (const float*)d_in[2];
    const float* bgcn = (const float*)d_in[3];
    const float* Wfc  = (const float*)d_in[4];
    const float* bfc  = (const float*)d_in[5];
    float* out = (float*)d_out;

    int n = in_sizes[0] / F;       // 100000
    int e = in_sizes[1] / 2;       // 1600000

    static bool attr_set = false;
    if (!attr_set) {
        cudaFuncSetAttribute(k_xw, cudaFuncAttributeMaxDynamicSharedMemorySize,
                             (F * C_OUT + 128 * F) * 4);
        attr_set = true;
    }

    int nbs = (n + 1023) / 1024;                       // scan blocks (98)

    k_setup<<<1024 + 1 + nbs, 256>>>(Wgcn, Wfc, bgcn, bfc, n);

    int hthreads = (e + 3) / 4;
    k_hist<<<(hthreads + 255) / 256, 256>>>(ei + e, e);

    k_scan1<<<nbs, 256>>>(n);
    k_scan2<<<1, 256>>>(nbs);
    k_scan3<<<nbs, 256>>>(n, e);

    int gemm_blocks = (n + 127) / 128;
    k_xw<<<gemm_blocks, 256, (F * C_OUT + 128 * F) * 4>>>(x, n);

    int fthreads = (e + 1) / 2;
    k_fill<<<(fthreads + 255) / 256, 256>>>(ei, e);

    k_gather<<<(n * 16 + 255) / 256, 256>>>(out, n);
}